// round 6
// baseline (speedup 1.0000x reference)
#include <cuda_runtime.h>
#include <cstdint>
#include <cstddef>

// ---------------------------------------------------------------------------
// WideLSTM: 16 independent LSTMs, I=H=128, B=32, T=512, fp32.
// out = [ output (B,T,N*H) | h_n (B,N*H) | c_n (B,N*H) ]
//
// Strategy: persistent fused kernel. 8 CTAs per LSTM (each owns a 16-wide
// h-chunk => 64 gate rows), weights resident in SMEM fp32, per-step
// z = W_ih*x_t + W_hh*h_{t-1} + b computed with packed fma.rn.f32x2.
// Cross-CTA h exchange via double-buffered global buffer + per-n spin barrier.
// ---------------------------------------------------------------------------

#define NLSTM 16
#define HSZ   128
#define ISZ   128
#define BSZ   32
#define TSZ   512
#define GPN   8      // CTAs per lstm
#define HCH   16     // H / GPN
#define NTHREADS 256
#define LROWS 64     // local gate rows per CTA (4 gates x 16)
#define WROW  132    // padded W row stride (floats), 132*4B = 33*16B

// shared memory layout (in floats)
#define OFF_WIH  0
#define OFF_WHH  (LROWS*WROW)
#define OFF_BIAS (2*LROWS*WROW)
#define OFF_XS   (OFF_BIAS + 64)              // double buffered x_t: 2 * 32*128
#define OFF_HS   (OFF_XS + 2*BSZ*128)         // h_{t-1}: 32*128
#define OFF_ZS   (OFF_HS + BSZ*128)           // z scratch: 64 rows * 33
#define SMEM_FLOATS (OFF_ZS + LROWS*33)
#define SMEM_BYTES  (SMEM_FLOATS * 4)

// scratch (static __device__ — no allocation)
__device__ float    g_hbuf[2][NLSTM][BSZ * HSZ];   // 512 KB
__device__ unsigned g_bar[NLSTM * 32];             // one counter per n, 128B apart

__global__ void init_kernel() {
    int i = threadIdx.x;
    if (i < NLSTM * 32) g_bar[i] = 0u;
}

__device__ __forceinline__ void fma2(unsigned long long &d,
                                     unsigned long long a,
                                     unsigned long long b) {
    asm("fma.rn.f32x2 %0, %1, %2, %0;" : "+l"(d) : "l"(a), "l"(b));
}

__device__ __forceinline__ float sigf(float z) {
    return __fdividef(1.0f, 1.0f + __expf(-z));
}
__device__ __forceinline__ float tanhfast(float z) {
    return __fdividef(2.0f, 1.0f + __expf(-2.0f * z)) - 1.0f;
}

// acc[0..3]: row r0 (batches bq*4..bq*4+3), acc[4..7]: row r0+1.
// Each acc holds (even-k partial, odd-k partial) packed f32x2.
__device__ __forceinline__ void gemm_phase(const float* __restrict__ w0p,
                                           const float* __restrict__ vb,
                                           int bq, unsigned long long* acc) {
#pragma unroll 8
    for (int k4 = 0; k4 < 32; ++k4) {
        ulonglong2 w0 = *reinterpret_cast<const ulonglong2*>(w0p + k4 * 4);
        ulonglong2 w1 = *reinterpret_cast<const ulonglong2*>(w0p + WROW + k4 * 4);
        int seg4 = ((k4 ^ bq) << 2);
#pragma unroll
        for (int j = 0; j < 4; ++j) {
            ulonglong2 v = *reinterpret_cast<const ulonglong2*>(
                vb + (4 * bq + j) * 128 + seg4);
            fma2(acc[j],     w0.x, v.x);
            fma2(acc[j],     w0.y, v.y);
            fma2(acc[4 + j], w1.x, v.x);
            fma2(acc[4 + j], w1.y, v.y);
        }
    }
}

// cp.async prefetch of x_t slice for lstm n into buffer (tt&1), swizzled.
__device__ __forceinline__ void prefetch_x(const float* __restrict__ x,
                                           float* sm, int n, int tid, int tt) {
    float* base = sm + OFF_XS + (tt & 1) * (BSZ * 128);
#pragma unroll
    for (int m = 0; m < 4; ++m) {
        int idx = tid + m * NTHREADS;
        int b = idx >> 5, k4 = idx & 31;
        int seg = k4 ^ ((b >> 2) & 7);
        const float* src = x + (size_t)(b * TSZ + tt) * (NLSTM * ISZ) + n * ISZ + k4 * 4;
        unsigned dst = (unsigned)__cvta_generic_to_shared(base + b * 128 + seg * 4);
        asm volatile("cp.async.cg.shared.global [%0], [%1], 16;"
                     :: "r"(dst), "l"(src) : "memory");
    }
}

__global__ void __launch_bounds__(NTHREADS, 1)
widelstm_kernel(const float* __restrict__ x,
                const float* __restrict__ Wih,
                const float* __restrict__ Whh,
                const float* __restrict__ bih,
                const float* __restrict__ bhh,
                float* __restrict__ out) {
    extern __shared__ float sm[];
    const int cta = blockIdx.x;
    const int n   = cta >> 3;
    const int g   = cta & 7;
    const int tid = threadIdx.x;
    const int rq  = tid >> 3;   // 0..31 -> rows 2rq, 2rq+1
    const int bq  = tid & 7;    // 0..7  -> batches 4bq..4bq+3

    // ---- load resident weights + bias into SMEM ----
    for (int idx = tid; idx < LROWS * 32; idx += NTHREADS) {
        int lr = idx >> 5, k4 = idx & 31;
        int q = lr >> 4, jh = lr & 15;
        int rg = q * HSZ + g * HCH + jh;
        float4 wi = *reinterpret_cast<const float4*>(
            Wih + ((size_t)n * 4 * HSZ + rg) * ISZ + k4 * 4);
        float4 wh = *reinterpret_cast<const float4*>(
            Whh + ((size_t)n * 4 * HSZ + rg) * HSZ + k4 * 4);
        *reinterpret_cast<float4*>(sm + OFF_WIH + lr * WROW + k4 * 4) = wi;
        *reinterpret_cast<float4*>(sm + OFF_WHH + lr * WROW + k4 * 4) = wh;
    }
    if (tid < LROWS) {
        int q = tid >> 4, jh = tid & 15;
        int rg = q * HSZ + g * HCH + jh;
        sm[OFF_BIAS + tid] = bih[n * 4 * HSZ + rg] + bhh[n * 4 * HSZ + rg];
    }

    // first x prefetch (t = 0)
    prefetch_x(x, sm, n, tid, 0);
    asm volatile("cp.async.commit_group;" ::: "memory");

    unsigned long long acc[8];
    float cst[2] = {0.0f, 0.0f};      // persistent c-state for this thread's cells
    const float* w_ih0 = sm + OFF_WIH + (rq * 2) * WROW;
    const float* w_hh0 = sm + OFF_WHH + (rq * 2) * WROW;
    unsigned* barp = g_bar + n * 32;

    for (int t = 0; t < TSZ; ++t) {
        // kick prefetch for t+1, then make sure buffer t is complete
        if (t + 1 < TSZ) {
            prefetch_x(x, sm, n, tid, t + 1);
            asm volatile("cp.async.commit_group;" ::: "memory");
            asm volatile("cp.async.wait_group 1;" ::: "memory");
        } else {
            asm volatile("cp.async.wait_group 0;" ::: "memory");
        }
        __syncthreads();   // xs[t&1] ready; also protects smem reuse

#pragma unroll
        for (int a = 0; a < 8; ++a) acc[a] = 0ull;

        // ---- x contribution: z += W_ih * x_t ----
        gemm_phase(w_ih0, sm + OFF_XS + (t & 1) * (BSZ * 128), bq, acc);

        // ---- h contribution (skip t=0: h0 == 0) ----
        if (t > 0) {
            unsigned target = 8u * (unsigned)t;
            unsigned v;
            do {
                asm volatile("ld.acquire.gpu.global.u32 %0, [%1];"
                             : "=r"(v) : "l"(barp) : "memory");
            } while (v < target);
            const float* hp = &g_hbuf[(t - 1) & 1][n][0];
#pragma unroll
            for (int m = 0; m < 4; ++m) {
                int idx = tid + m * NTHREADS;
                int b = idx >> 5, k4 = idx & 31;
                int seg = k4 ^ ((b >> 2) & 7);
                float4 vv = *reinterpret_cast<const float4*>(hp + b * 128 + k4 * 4);
                *reinterpret_cast<float4*>(sm + OFF_HS + b * 128 + seg * 4) = vv;
            }
            __syncthreads();
            gemm_phase(w_hh0, sm + OFF_HS, bq, acc);
        }

        // ---- horizontal add + bias -> z_s ----
#pragma unroll
        for (int s = 0; s < 2; ++s) {
            float bias = sm[OFF_BIAS + rq * 2 + s];
#pragma unroll
            for (int j = 0; j < 4; ++j) {
                unsigned long long a = acc[s * 4 + j];
                float lo = __uint_as_float((unsigned)a);
                float hi = __uint_as_float((unsigned)(a >> 32));
                sm[OFF_ZS + (rq * 2 + s) * 33 + bq * 4 + j] = lo + hi + bias;
            }
        }
        __syncthreads();

        // ---- gate combine + state update + outputs ----
#pragma unroll
        for (int m = 0; m < 2; ++m) {
            int cell = tid + m * NTHREADS;       // cell = b*16 + jh
            int b = cell >> 4, jh = cell & 15;
            float zi = sm[OFF_ZS + (jh)      * 33 + b];
            float zf = sm[OFF_ZS + (16 + jh) * 33 + b];
            float zg = sm[OFF_ZS + (32 + jh) * 33 + b];
            float zo = sm[OFF_ZS + (48 + jh) * 33 + b];
            float ig = sigf(zi);
            float fg = sigf(zf);
            float gg = tanhfast(zg);
            float og = sigf(zo);
            float c = fg * cst[m] + ig * gg;
            cst[m] = c;
            float h = og * tanhfast(c);
            int col = g * HCH + jh;
            out[(size_t)(b * TSZ + t) * (NLSTM * HSZ) + n * HSZ + col] = h;
            g_hbuf[t & 1][n][b * 128 + col] = h;
            if (t == TSZ - 1) {
                size_t base = (size_t)BSZ * TSZ * NLSTM * HSZ;
                out[base + (size_t)b * NLSTM * HSZ + n * HSZ + col] = h;
                out[base + (size_t)BSZ * NLSTM * HSZ
                         + (size_t)b * NLSTM * HSZ + n * HSZ + col] = c;
            }
        }

        // ---- publish h(t): fence all stores, then one release-arrive ----
        __threadfence();
        __syncthreads();
        if (tid == 0) atomicAdd(barp, 1u);
    }
}

extern "C" void kernel_launch(void* const* d_in, const int* in_sizes, int n_in,
                              void* d_out, int out_size) {
    (void)in_sizes; (void)n_in; (void)out_size;
    const float* x   = (const float*)d_in[0];
    const float* Wih = (const float*)d_in[1];
    const float* Whh = (const float*)d_in[2];
    const float* bih = (const float*)d_in[3];
    const float* bhh = (const float*)d_in[4];
    float* out = (float*)d_out;

    cudaFuncSetAttribute(widelstm_kernel,
                         cudaFuncAttributeMaxDynamicSharedMemorySize, SMEM_BYTES);

    init_kernel<<<1, 512>>>();
    widelstm_kernel<<<NLSTM * GPN, NTHREADS, SMEM_BYTES>>>(x, Wih, Whh, bih, bhh, out);
}